// round 2
// baseline (speedup 1.0000x reference)
#include <cuda_runtime.h>

// attention scalar per pixel, computed by k1, consumed by k2
__device__ float g_a[12544];

#define BM 32
#define BN 64
#define KC 32

// ---------------------------------------------------------------------------
// Kernel 1: fused  h1 = relu(x@W1+b1) -> ... -> a = sigmoid(.)  per pixel.
// GEMM tile: 32 pixels x 64 outputs, K=2048 in chunks of 32.
// 128 threads, 4x4 register tile each. Tail MLP (64->16->8->1) on warp 0.
// ---------------------------------------------------------------------------
__global__ void __launch_bounds__(128) k1_mlp(
    const float* __restrict__ x,
    const float* __restrict__ W1, const float* __restrict__ b1,
    const float* __restrict__ W2, const float* __restrict__ b2,
    const float* __restrict__ W3, const float* __restrict__ b3,
    const float* __restrict__ W4, const float* __restrict__ b4)
{
    __shared__ float sX[KC][BM + 1];   // [k][m], pad to 33 -> conflict-free
    __shared__ float sW[KC * BN];      // [k][n] contiguous
    __shared__ float sH[BM][BN + 1];   // h1 tile for the tail MLP
    __shared__ float sW2[64 * 16];
    __shared__ float sW3[16 * 8];
    __shared__ float sW4[8];

    const int tid = threadIdx.x;

    // stage small weights once
    for (int i = tid; i < 64 * 16; i += 128) sW2[i] = W2[i];
    if (tid < 128) sW3[tid] = W3[tid];     // 16*8 = 128
    if (tid < 8)   sW4[tid] = W4[tid];

    const int m_base = blockIdx.x * BM;
    const int tx = tid & 15;   // n direction, 0..15 -> n0 = tx*4
    const int ty = tid >> 4;   // m direction, 0..7  -> m0 = ty*4

    float acc[4][4];
#pragma unroll
    for (int i = 0; i < 4; i++)
#pragma unroll
        for (int j = 0; j < 4; j++) acc[i][j] = 0.f;

    const float* xrow = x + (size_t)m_base * 2048;

    for (int k0 = 0; k0 < 2048; k0 += KC) {
        // load X tile: 32 pixels x 32 k = 256 float4, 2 per thread
#pragma unroll
        for (int r = 0; r < 2; r++) {
            int s = tid + r * 128;
            int m = s >> 3;        // pixel within tile
            int q = s & 7;         // float4 index along k
            float4 v = *(const float4*)(xrow + (size_t)m * 2048 + k0 + q * 4);
            sX[q * 4 + 0][m] = v.x;
            sX[q * 4 + 1][m] = v.y;
            sX[q * 4 + 2][m] = v.z;
            sX[q * 4 + 3][m] = v.w;
        }
        // load W1 chunk: contiguous 2048 floats = 512 float4, 4 per thread
        {
            const float4* wsrc = (const float4*)(W1 + (size_t)k0 * 64);
            float4* wdst = (float4*)sW;
#pragma unroll
            for (int r = 0; r < 4; r++) wdst[tid + r * 128] = wsrc[tid + r * 128];
        }
        __syncthreads();

#pragma unroll
        for (int k = 0; k < KC; k++) {
            float a0 = sX[k][ty * 4 + 0];
            float a1 = sX[k][ty * 4 + 1];
            float a2 = sX[k][ty * 4 + 2];
            float a3 = sX[k][ty * 4 + 3];
            float4 bv = *(const float4*)(sW + k * 64 + tx * 4);
            acc[0][0] += a0 * bv.x; acc[0][1] += a0 * bv.y; acc[0][2] += a0 * bv.z; acc[0][3] += a0 * bv.w;
            acc[1][0] += a1 * bv.x; acc[1][1] += a1 * bv.y; acc[1][2] += a1 * bv.z; acc[1][3] += a1 * bv.w;
            acc[2][0] += a2 * bv.x; acc[2][1] += a2 * bv.y; acc[2][2] += a2 * bv.z; acc[2][3] += a2 * bv.w;
            acc[3][0] += a3 * bv.x; acc[3][1] += a3 * bv.y; acc[3][2] += a3 * bv.z; acc[3][3] += a3 * bv.w;
        }
        __syncthreads();
    }

    // bias + relu -> sH
#pragma unroll
    for (int i = 0; i < 4; i++) {
#pragma unroll
        for (int j = 0; j < 4; j++) {
            float v = acc[i][j] + b1[tx * 4 + j];
            sH[ty * 4 + i][tx * 4 + j] = fmaxf(v, 0.f);
        }
    }
    __syncthreads();

    // tail MLP: one pixel per thread, warp 0 only
    if (tid < BM) {
        const int m = tid;
        float h2[16];
#pragma unroll
        for (int j = 0; j < 16; j++) h2[j] = b2[j];
        for (int n = 0; n < 64; n++) {
            float hv = sH[m][n];
#pragma unroll
            for (int j = 0; j < 16; j++) h2[j] += hv * sW2[n * 16 + j];
        }
        float h3[8];
#pragma unroll
        for (int j = 0; j < 8; j++) h3[j] = b3[j];
#pragma unroll
        for (int n = 0; n < 16; n++) {
            float hv = fmaxf(h2[n], 0.f);
#pragma unroll
            for (int j = 0; j < 8; j++) h3[j] += hv * sW3[n * 8 + j];
        }
        float z = b4[0];
#pragma unroll
        for (int n = 0; n < 8; n++) z += fmaxf(h3[n], 0.f) * sW4[n];
        g_a[m_base + m] = 1.f / (1.f + __expf(-z));
    }
}

// ---------------------------------------------------------------------------
// Kernel 2: out[b,c] = sum_p a[b,p]*x[b,p,c] / sum_p a[b,p]
// grid: 64 batches x 2 channel halves, 256 threads, float4 per thread.
// ---------------------------------------------------------------------------
__global__ void __launch_bounds__(256) k2_reduce(
    const float* __restrict__ x, float* __restrict__ out)
{
    __shared__ float sa[196];
    const int b    = blockIdx.x >> 1;
    const int half = blockIdx.x & 1;
    const int tid  = threadIdx.x;

    if (tid < 196) sa[tid] = g_a[b * 196 + tid];
    __syncthreads();

    const int c = half * 1024 + tid * 4;
    const float4* xp = (const float4*)(x + (size_t)b * 196 * 2048 + c);

    float4 acc = make_float4(0.f, 0.f, 0.f, 0.f);
    float mask = 0.f;
#pragma unroll 4
    for (int p = 0; p < 196; p++) {
        float ap = sa[p];
        float4 v = xp[(size_t)p * 512];
        acc.x += ap * v.x;
        acc.y += ap * v.y;
        acc.z += ap * v.z;
        acc.w += ap * v.w;
        mask += ap;
    }
    float inv = 1.f / mask;
    float4 o = make_float4(acc.x * inv, acc.y * inv, acc.z * inv, acc.w * inv);
    *(float4*)(out + (size_t)b * 2048 + c) = o;
}

extern "C" void kernel_launch(void* const* d_in, const int* in_sizes, int n_in,
                              void* d_out, int out_size)
{
    const float* x  = (const float*)d_in[0];
    const float* W1 = (const float*)d_in[1];
    const float* b1 = (const float*)d_in[2];
    const float* W2 = (const float*)d_in[3];
    const float* b2 = (const float*)d_in[4];
    const float* W3 = (const float*)d_in[5];
    const float* b3 = (const float*)d_in[6];
    const float* W4 = (const float*)d_in[7];
    const float* b4 = (const float*)d_in[8];
    float* out = (float*)d_out;

    k1_mlp<<<12544 / BM, 128>>>(x, W1, b1, W2, b2, W3, b3, W4, b4);
    k2_reduce<<<128, 256>>>(x, out);
}

// round 3
// speedup vs baseline: 1.9161x; 1.9161x over previous
#include <cuda_runtime.h>
#include <cuda_bf16.h>
#include <cstdint>

// ---------------------------------------------------------------------------
// Device-global scratch (allocation-free)
// ---------------------------------------------------------------------------
__device__ float g_a[12544];                         // attention scalar per pixel
__device__ __align__(16) __nv_bfloat16 gW1hi[2048 * 64];
__device__ __align__(16) __nv_bfloat16 gW1lo[2048 * 64];

// ---------------------------------------------------------------------------
// PTX helpers
// ---------------------------------------------------------------------------
__device__ __forceinline__ uint32_t smem_u32(const void* p) {
    return (uint32_t)__cvta_generic_to_shared(p);
}
__device__ __forceinline__ void ldsm4(uint32_t& r0, uint32_t& r1, uint32_t& r2, uint32_t& r3, uint32_t a) {
    asm volatile("ldmatrix.sync.aligned.m8n8.x4.shared.b16 {%0,%1,%2,%3},[%4];"
                 : "=r"(r0), "=r"(r1), "=r"(r2), "=r"(r3) : "r"(a));
}
__device__ __forceinline__ void ldsm4t(uint32_t& r0, uint32_t& r1, uint32_t& r2, uint32_t& r3, uint32_t a) {
    asm volatile("ldmatrix.sync.aligned.m8n8.x4.trans.shared.b16 {%0,%1,%2,%3},[%4];"
                 : "=r"(r0), "=r"(r1), "=r"(r2), "=r"(r3) : "r"(a));
}
__device__ __forceinline__ void mma_bf16(float* c, const uint32_t* a, uint32_t b0, uint32_t b1) {
    asm volatile(
        "mma.sync.aligned.m16n8k16.row.col.f32.bf16.bf16.f32 "
        "{%0,%1,%2,%3},{%4,%5,%6,%7},{%8,%9},{%0,%1,%2,%3};"
        : "+f"(c[0]), "+f"(c[1]), "+f"(c[2]), "+f"(c[3])
        : "r"(a[0]), "r"(a[1]), "r"(a[2]), "r"(a[3]), "r"(b0), "r"(b1));
}
__device__ __forceinline__ uint32_t pack_bf2(__nv_bfloat16 lo, __nv_bfloat16 hi) {
    return ((uint32_t)__bfloat16_as_ushort(hi) << 16) | (uint32_t)__bfloat16_as_ushort(lo);
}
__device__ __forceinline__ void split2(float f0, float f1, uint32_t& hi, uint32_t& lo) {
    __nv_bfloat16 h0 = __float2bfloat16_rn(f0);
    __nv_bfloat16 h1 = __float2bfloat16_rn(f1);
    __nv_bfloat16 l0 = __float2bfloat16_rn(f0 - __bfloat162float(h0));
    __nv_bfloat16 l1 = __float2bfloat16_rn(f1 - __bfloat162float(h1));
    hi = pack_bf2(h0, h1);
    lo = pack_bf2(l0, l1);
}

// ---------------------------------------------------------------------------
// k0: one-shot split of W1 into bf16 hi/lo  (2048*64 elems)
// ---------------------------------------------------------------------------
__global__ void k0_convW(const float* __restrict__ W1) {
    int i = blockIdx.x * blockDim.x + threadIdx.x;
    if (i < 2048 * 64) {
        float w = W1[i];
        __nv_bfloat16 h = __float2bfloat16_rn(w);
        gW1hi[i] = h;
        gW1lo[i] = __float2bfloat16_rn(w - __bfloat162float(h));
    }
}

// ---------------------------------------------------------------------------
// k1: fused MLP via bf16-split tensor-core GEMM (layer 1) + scalar tail.
// Tile: 32 pixels x 64 outputs, K in chunks of 32. 128 threads = 2x2 warps,
// each warp m16 x n32 via mma.m16n8k16 (3 mma per frag: hh + hl + lh).
// ---------------------------------------------------------------------------
__global__ void __launch_bounds__(128) k1_mlp(
    const float* __restrict__ x,
    const float* __restrict__ b1,
    const float* __restrict__ W2, const float* __restrict__ b2,
    const float* __restrict__ W3, const float* __restrict__ b3,
    const float* __restrict__ W4, const float* __restrict__ b4)
{
    __shared__ __align__(16) __nv_bfloat16 sAhi[32][40];
    __shared__ __align__(16) __nv_bfloat16 sAlo[32][40];
    __shared__ __align__(16) __nv_bfloat16 sBhi[32][72];
    __shared__ __align__(16) __nv_bfloat16 sBlo[32][72];
    __shared__ float sH[32][65];
    __shared__ float sB1[64];
    __shared__ float sW2[64 * 16];
    __shared__ float sW3[16 * 8];
    __shared__ float sW4[8];

    const int tid  = threadIdx.x;
    const int lane = tid & 31;
    const int warp = tid >> 5;
    const int wm   = warp >> 1;       // 0..1 -> m offset wm*16
    const int wn   = warp & 1;        // 0..1 -> n offset wn*32
    const int nb   = wn * 32;

    // stage small weights
    for (int i = tid; i < 64 * 16; i += 128) sW2[i] = W2[i];
    if (tid < 128) sW3[tid] = W3[tid];
    if (tid < 64)  sB1[tid] = b1[tid];
    if (tid < 8)   sW4[tid] = W4[tid];

    const int m_base = blockIdx.x * 32;

    // lane-derived ldmatrix address components
    const int lkr = (lane & 7) + ((lane >> 3) & 1) * 8;  // 0..15
    const int lnc = (lane >> 4) * 8;                      // 0 or 8

    float acc[4][4];
#pragma unroll
    for (int j = 0; j < 4; j++)
#pragma unroll
        for (int i = 0; i < 4; i++) acc[j][i] = 0.f;

    // per-thread staging coords
    const int am = tid >> 2;           // pixel row in tile (0..31)
    const int ak = (tid & 3) * 8;      // k seg within chunk
    const int br = tid >> 2;           // W row in chunk (0..31)
    const int bs = (tid & 3) * 16;     // bf16 col seg

    for (int k0 = 0; k0 < 2048; k0 += 32) {
        // stage X chunk (fp32 -> bf16 hi/lo)
        {
            const float4* p = (const float4*)(x + (size_t)(m_base + am) * 2048 + k0 + ak);
            float4 v0 = p[0];
            float4 v1 = p[1];
            uint32_t h, l;
            split2(v0.x, v0.y, h, l);
            *(uint32_t*)&sAhi[am][ak + 0] = h; *(uint32_t*)&sAlo[am][ak + 0] = l;
            split2(v0.z, v0.w, h, l);
            *(uint32_t*)&sAhi[am][ak + 2] = h; *(uint32_t*)&sAlo[am][ak + 2] = l;
            split2(v1.x, v1.y, h, l);
            *(uint32_t*)&sAhi[am][ak + 4] = h; *(uint32_t*)&sAlo[am][ak + 4] = l;
            split2(v1.z, v1.w, h, l);
            *(uint32_t*)&sAhi[am][ak + 6] = h; *(uint32_t*)&sAlo[am][ak + 6] = l;
        }
        // stage W1 chunk (pre-split bf16)
        {
            const uint4* ph = (const uint4*)(gW1hi + (size_t)(k0 + br) * 64 + bs);
            const uint4* pl = (const uint4*)(gW1lo + (size_t)(k0 + br) * 64 + bs);
            *(uint4*)&sBhi[br][bs]     = ph[0];
            *(uint4*)&sBhi[br][bs + 8] = ph[1];
            *(uint4*)&sBlo[br][bs]     = pl[0];
            *(uint4*)&sBlo[br][bs + 8] = pl[1];
        }
        __syncthreads();

#pragma unroll
        for (int kk = 0; kk < 32; kk += 16) {
            uint32_t ah[4], al[4];
            ldsm4(ah[0], ah[1], ah[2], ah[3], smem_u32(&sAhi[wm * 16 + lkr][kk + lnc]));
            ldsm4(al[0], al[1], al[2], al[3], smem_u32(&sAlo[wm * 16 + lkr][kk + lnc]));
            uint32_t bh[8], bl[8];
            ldsm4t(bh[0], bh[1], bh[2], bh[3], smem_u32(&sBhi[kk + lkr][nb + lnc]));
            ldsm4t(bh[4], bh[5], bh[6], bh[7], smem_u32(&sBhi[kk + lkr][nb + 16 + lnc]));
            ldsm4t(bl[0], bl[1], bl[2], bl[3], smem_u32(&sBlo[kk + lkr][nb + lnc]));
            ldsm4t(bl[4], bl[5], bl[6], bl[7], smem_u32(&sBlo[kk + lkr][nb + 16 + lnc]));
#pragma unroll
            for (int j = 0; j < 4; j++) {
                mma_bf16(acc[j], ah, bh[2 * j], bh[2 * j + 1]);   // hi*hi
                mma_bf16(acc[j], ah, bl[2 * j], bl[2 * j + 1]);   // hi*lo
                mma_bf16(acc[j], al, bh[2 * j], bh[2 * j + 1]);   // lo*hi
            }
        }
        __syncthreads();
    }

    // epilogue: bias + relu -> sH
    {
        const int row = wm * 16 + (lane >> 2);
#pragma unroll
        for (int j = 0; j < 4; j++) {
            const int nc = nb + j * 8 + (lane & 3) * 2;
            sH[row][nc]         = fmaxf(acc[j][0] + sB1[nc],     0.f);
            sH[row][nc + 1]     = fmaxf(acc[j][1] + sB1[nc + 1], 0.f);
            sH[row + 8][nc]     = fmaxf(acc[j][2] + sB1[nc],     0.f);
            sH[row + 8][nc + 1] = fmaxf(acc[j][3] + sB1[nc + 1], 0.f);
        }
    }
    __syncthreads();

    // tail MLP: 64->16->8->1 + sigmoid, one pixel per thread on warp 0
    if (tid < 32) {
        const int m = tid;
        float h2[16];
#pragma unroll
        for (int j = 0; j < 16; j++) h2[j] = b2[j];
        for (int n = 0; n < 64; n++) {
            float hv = sH[m][n];
#pragma unroll
            for (int j = 0; j < 16; j++) h2[j] += hv * sW2[n * 16 + j];
        }
        float h3[8];
#pragma unroll
        for (int j = 0; j < 8; j++) h3[j] = b3[j];
#pragma unroll
        for (int n = 0; n < 16; n++) {
            float hv = fmaxf(h2[n], 0.f);
#pragma unroll
            for (int j = 0; j < 8; j++) h3[j] += hv * sW3[n * 8 + j];
        }
        float z = b4[0];
#pragma unroll
        for (int n = 0; n < 8; n++) z += fmaxf(h3[n], 0.f) * sW4[n];
        g_a[m_base + m] = 1.f / (1.f + __expf(-z));
    }
}

// ---------------------------------------------------------------------------
// k2: out[b,c] = sum_p a*x / sum_p a.  512 blocks (64 b x 8 chunks), scalar
// coalesced loads, deep unroll for MLP.
// ---------------------------------------------------------------------------
__global__ void __launch_bounds__(256) k2_reduce(
    const float* __restrict__ x, float* __restrict__ out)
{
    __shared__ float sa[196];
    const int b  = blockIdx.x >> 3;
    const int ch = ((blockIdx.x & 7) << 8) + threadIdx.x;

    if (threadIdx.x < 196) sa[threadIdx.x] = g_a[b * 196 + threadIdx.x];
    __syncthreads();

    const float* xp = x + (size_t)b * 196 * 2048 + ch;
    float acc = 0.f, mask = 0.f;
#pragma unroll 14
    for (int p = 0; p < 196; p++) {
        float ap = sa[p];
        acc  += ap * xp[(size_t)p * 2048];
        mask += ap;
    }
    out[b * 2048 + ch] = acc / mask;
}

extern "C" void kernel_launch(void* const* d_in, const int* in_sizes, int n_in,
                              void* d_out, int out_size)
{
    const float* x  = (const float*)d_in[0];
    const float* W1 = (const float*)d_in[1];
    const float* b1 = (const float*)d_in[2];
    const float* W2 = (const float*)d_in[3];
    const float* b2 = (const float*)d_in[4];
    const float* W3 = (const float*)d_in[5];
    const float* b3 = (const float*)d_in[6];
    const float* W4 = (const float*)d_in[7];
    const float* b4 = (const float*)d_in[8];
    float* out = (float*)d_out;

    k0_convW<<<512, 256>>>(W1);
    k1_mlp<<<392, 128>>>(x, b1, W2, b2, W3, b3, W4, b4);
    k2_reduce<<<512, 256>>>(x, out);
}

// round 6
// speedup vs baseline: 1.9771x; 1.0319x over previous
#include <cuda_runtime.h>
#include <cuda_bf16.h>
#include <cstdint>

// ---------------------------------------------------------------------------
// Device-global scratch (allocation-free)
// ---------------------------------------------------------------------------
__device__ float g_a[12544];      // attention scalar per pixel

// ---------------------------------------------------------------------------
// Helpers
// ---------------------------------------------------------------------------
__device__ __forceinline__ uint32_t smem_u32(const void* p) {
    return (uint32_t)__cvta_generic_to_shared(p);
}
__device__ __forceinline__ void ldsm4(uint32_t& r0, uint32_t& r1, uint32_t& r2, uint32_t& r3, uint32_t a) {
    asm volatile("ldmatrix.sync.aligned.m8n8.x4.shared.b16 {%0,%1,%2,%3},[%4];"
                 : "=r"(r0), "=r"(r1), "=r"(r2), "=r"(r3) : "r"(a));
}
__device__ __forceinline__ void ldsm4t(uint32_t& r0, uint32_t& r1, uint32_t& r2, uint32_t& r3, uint32_t a) {
    asm volatile("ldmatrix.sync.aligned.m8n8.x4.trans.shared.b16 {%0,%1,%2,%3},[%4];"
                 : "=r"(r0), "=r"(r1), "=r"(r2), "=r"(r3) : "r"(a));
}
__device__ __forceinline__ void mma_bf16(float* c, const uint32_t* a, uint32_t b0, uint32_t b1) {
    asm volatile(
        "mma.sync.aligned.m16n8k16.row.col.f32.bf16.bf16.f32 "
        "{%0,%1,%2,%3},{%4,%5,%6,%7},{%8,%9},{%0,%1,%2,%3};"
        : "+f"(c[0]), "+f"(c[1]), "+f"(c[2]), "+f"(c[3])
        : "r"(a[0]), "r"(a[1]), "r"(a[2]), "r"(a[3]), "r"(b0), "r"(b1));
}
__device__ __forceinline__ uint32_t pack_hi2(float a, float b) {
    __nv_bfloat16 ha = __float2bfloat16_rn(a);
    __nv_bfloat16 hb = __float2bfloat16_rn(b);
    return ((uint32_t)__bfloat16_as_ushort(hb) << 16) | (uint32_t)__bfloat16_as_ushort(ha);
}
__device__ __forceinline__ uint32_t pack_lo2(float a, float b) {
    __nv_bfloat16 ha = __float2bfloat16_rn(a);
    __nv_bfloat16 hb = __float2bfloat16_rn(b);
    __nv_bfloat16 la = __float2bfloat16_rn(a - __bfloat162float(ha));
    __nv_bfloat16 lb = __float2bfloat16_rn(b - __bfloat162float(hb));
    return ((uint32_t)__bfloat16_as_ushort(lb) << 16) | (uint32_t)__bfloat16_as_ushort(la);
}

// ---------------------------------------------------------------------------
// Tiling constants.  Tile: 64 pixels x 64 outputs, K-chunk 32, 128 threads.
// ---------------------------------------------------------------------------
#define APITCH 40                 // halves per A row (32 + 8 pad)
#define BPITCH 72                 // halves per B row (64 + 8 pad)
#define AHI 0                     // byte offsets within one stage
#define ALO 5120                  // 64*40*2
#define BHI 10240
#define BLO 14848                 // + 32*72*2
#define STG 19456                 // bytes per stage

__global__ void __launch_bounds__(128) k1_mlp(
    const float* __restrict__ x,
    const float* __restrict__ W1, const float* __restrict__ b1,
    const float* __restrict__ W2, const float* __restrict__ b2,
    const float* __restrict__ W3, const float* __restrict__ b3,
    const float* __restrict__ W4, const float* __restrict__ b4)
{
    __shared__ __align__(16) char sStage[2][STG];   // 38912 B
    __shared__ float sW2[64 * 16];
    __shared__ float sW3[16 * 8];
    __shared__ float sW4[8];
    __shared__ float sB1[64];

    const int tid  = threadIdx.x;
    const int lane = tid & 31;
    const int warp = tid >> 5;
    const int wm16 = warp * 16;                 // warp's m offset (4 warps x 16 rows)
    const int m_base = blockIdx.x * 64;

    // ldsm lane addressing (proven in earlier rounds)
    const int lkr = (lane & 7) + ((lane >> 3) & 1) * 8;   // 0..15
    const int lnc = (lane >> 4) * 8;                       // 0 or 8

    // staging coords
    const int a_row = tid >> 1;                 // 0..63
    const int a_kq  = (tid & 1) * 16;           // k offset {0,16}
    const int b_row = tid >> 2;                 // 0..31 (k within chunk)
    const int b_seg = (tid & 3) * 16;           // n offset {0,16,32,48}

    // stage small weights
    for (int i = tid; i < 64 * 16; i += 128) sW2[i] = W2[i];
    if (tid < 128) sW3[tid] = W3[tid];
    if (tid < 64)  sB1[tid] = b1[tid];
    if (tid < 8)   sW4[tid] = W4[tid];

    float acc[8][4];
#pragma unroll
    for (int j = 0; j < 8; j++)
#pragma unroll
        for (int i = 0; i < 4; i++) acc[j][i] = 0.f;

    const float* aBase = x  + (size_t)(m_base + a_row) * 2048 + a_kq;
    const float* bBase = W1 + (size_t)b_row * 64 + b_seg;

    float4 ra[4], rb[4];

    // ---- LDG / STS helpers (lambdas keep register naming tight) ----
    auto ldg_chunk = [&](int i) {
        const float4* ap = (const float4*)(aBase + (size_t)i * 32);
        const float4* bp = (const float4*)(bBase + (size_t)i * 32 * 64);
#pragma unroll
        for (int j = 0; j < 4; j++) ra[j] = ap[j];
#pragma unroll
        for (int j = 0; j < 4; j++) rb[j] = bp[j];
    };
    auto sts_chunk = [&](int buf) {
        char* st = sStage[buf];
        // A: row a_row, k a_kq..a_kq+15
        {
            uint32_t off = (uint32_t)(a_row * APITCH + a_kq) * 2;
            uint4 h0 = make_uint4(pack_hi2(ra[0].x, ra[0].y), pack_hi2(ra[0].z, ra[0].w),
                                  pack_hi2(ra[1].x, ra[1].y), pack_hi2(ra[1].z, ra[1].w));
            uint4 h1 = make_uint4(pack_hi2(ra[2].x, ra[2].y), pack_hi2(ra[2].z, ra[2].w),
                                  pack_hi2(ra[3].x, ra[3].y), pack_hi2(ra[3].z, ra[3].w));
            uint4 l0 = make_uint4(pack_lo2(ra[0].x, ra[0].y), pack_lo2(ra[0].z, ra[0].w),
                                  pack_lo2(ra[1].x, ra[1].y), pack_lo2(ra[1].z, ra[1].w));
            uint4 l1 = make_uint4(pack_lo2(ra[2].x, ra[2].y), pack_lo2(ra[2].z, ra[2].w),
                                  pack_lo2(ra[3].x, ra[3].y), pack_lo2(ra[3].z, ra[3].w));
            *(uint4*)(st + AHI + off)      = h0;
            *(uint4*)(st + AHI + off + 16) = h1;
            *(uint4*)(st + ALO + off)      = l0;
            *(uint4*)(st + ALO + off + 16) = l1;
        }
        // B: row b_row (k), n b_seg..b_seg+15
        {
            uint32_t off = (uint32_t)(b_row * BPITCH + b_seg) * 2;
            uint4 h0 = make_uint4(pack_hi2(rb[0].x, rb[0].y), pack_hi2(rb[0].z, rb[0].w),
                                  pack_hi2(rb[1].x, rb[1].y), pack_hi2(rb[1].z, rb[1].w));
            uint4 h1 = make_uint4(pack_hi2(rb[2].x, rb[2].y), pack_hi2(rb[2].z, rb[2].w),
                                  pack_hi2(rb[3].x, rb[3].y), pack_hi2(rb[3].z, rb[3].w));
            uint4 l0 = make_uint4(pack_lo2(rb[0].x, rb[0].y), pack_lo2(rb[0].z, rb[0].w),
                                  pack_lo2(rb[1].x, rb[1].y), pack_lo2(rb[1].z, rb[1].w));
            uint4 l1 = make_uint4(pack_lo2(rb[2].x, rb[2].y), pack_lo2(rb[2].z, rb[2].w),
                                  pack_lo2(rb[3].x, rb[3].y), pack_lo2(rb[3].z, rb[3].w));
            *(uint4*)(st + BHI + off)      = h0;
            *(uint4*)(st + BHI + off + 16) = h1;
            *(uint4*)(st + BLO + off)      = l0;
            *(uint4*)(st + BLO + off + 16) = l1;
        }
    };

    // ---- prologue: chunk 0 staged, chunk 1 in regs ----
    ldg_chunk(0);
    sts_chunk(0);
    __syncthreads();
    ldg_chunk(1);

    // ---- pipelined mainloop over 64 K-chunks ----
    for (int i = 0; i < 64; i++) {
        const int cur = i & 1;
        if (i < 63) sts_chunk(cur ^ 1);       // stage chunk i+1 (regs -> other buf)
        if (i < 62) ldg_chunk(i + 2);         // prefetch chunk i+2

        const uint32_t sb = smem_u32(sStage[cur]);
#pragma unroll
        for (int kk = 0; kk < 32; kk += 16) {
            uint32_t ah[4], al[4];
            {
                uint32_t ao = sb + AHI + (uint32_t)((wm16 + lkr) * APITCH + kk + lnc) * 2;
                ldsm4(ah[0], ah[1], ah[2], ah[3], ao);
                ldsm4(al[0], al[1], al[2], al[3], ao + (ALO - AHI));
            }
#pragma unroll
            for (int h = 0; h < 2; h++) {     // two n32 halves
                uint32_t bh[8], bl[8];
                uint32_t bo = sb + BHI + (uint32_t)((kk + lkr) * BPITCH + h * 32 + lnc) * 2;
                ldsm4t(bh[0], bh[1], bh[2], bh[3], bo);
                ldsm4t(bh[4], bh[5], bh[6], bh[7], bo + 32);
                ldsm4t(bl[0], bl[1], bl[2], bl[3], bo + (BLO - BHI));
                ldsm4t(bl[4], bl[5], bl[6], bl[7], bo + (BLO - BHI) + 32);
#pragma unroll
                for (int j = 0; j < 4; j++) {
                    float* c = acc[h * 4 + j];
                    mma_bf16(c, ah, bh[2 * j], bh[2 * j + 1]);   // hi*hi
                    mma_bf16(c, ah, bl[2 * j], bl[2 * j + 1]);   // hi*lo
                    mma_bf16(c, al, bh[2 * j], bh[2 * j + 1]);   // lo*hi
                }
            }
        }
        __syncthreads();
    }

    // ---- epilogue: bias + relu -> sH (aliased onto stage buffers) ----
    float* sH = (float*)sStage[0];            // [64][65]
    {
        const int r0 = wm16 + (lane >> 2);
        const int c0 = (lane & 3) * 2;
#pragma unroll
        for (int j = 0; j < 8; j++) {
            const int n = j * 8 + c0;
            sH[r0 * 65 + n]           = fmaxf(acc[j][0] + sB1[n],     0.f);
            sH[r0 * 65 + n + 1]       = fmaxf(acc[j][1] + sB1[n + 1], 0.f);
            sH[(r0 + 8) * 65 + n]     = fmaxf(acc[j][2] + sB1[n],     0.f);
            sH[(r0 + 8) * 65 + n + 1] = fmaxf(acc[j][3] + sB1[n + 1], 0.f);
        }
    }
    __syncthreads();

    // ---- tail MLP: 64->16->8->1 + sigmoid, one pixel per thread ----
    if (tid < 64) {
        const int m = tid;
        float h2[16];
#pragma unroll
        for (int j = 0; j < 16; j++) h2[j] = b2[j];
#pragma unroll 8
        for (int n = 0; n < 64; n++) {
            float hv = sH[m * 65 + n];
#pragma unroll
            for (int j = 0; j < 16; j++) h2[j] += hv * sW2[n * 16 + j];
        }
        float h3[8];
#pragma unroll
        for (int j = 0; j < 8; j++) h3[j] = b3[j];
#pragma unroll
        for (int n = 0; n < 16; n++) {
            float hv = fmaxf(h2[n], 0.f);
#pragma unroll
            for (int j = 0; j < 8; j++) h3[j] += hv * sW3[n * 8 + j];
        }
        float z = b4[0];
#pragma unroll
        for (int n = 0; n < 8; n++) z += fmaxf(h3[n], 0.f) * sW4[n];
        g_a[m_base + m] = 1.f / (1.f + __expf(-z));
    }
}

// ---------------------------------------------------------------------------
// k2: out[b,c] = sum_p a*x / sum_p a.  512 blocks (64 b x 8 chunks).
// ---------------------------------------------------------------------------
__global__ void __launch_bounds__(256) k2_reduce(
    const float* __restrict__ x, float* __restrict__ out)
{
    __shared__ float sa[196];
    const int b  = blockIdx.x >> 3;
    const int ch = ((blockIdx.x & 7) << 8) + threadIdx.x;

    if (threadIdx.x < 196) sa[threadIdx.x] = g_a[b * 196 + threadIdx.x];
    __syncthreads();

    const float* xp = x + (size_t)b * 196 * 2048 + ch;
    float acc = 0.f, mask = 0.f;
#pragma unroll 14
    for (int p = 0; p < 196; p++) {
        float ap = sa[p];
        acc  += ap * xp[(size_t)p * 2048];
        mask += ap;
    }
    out[b * 2048 + ch] = acc / mask;
}

extern "C" void kernel_launch(void* const* d_in, const int* in_sizes, int n_in,
                              void* d_out, int out_size)
{
    const float* x  = (const float*)d_in[0];
    const float* W1 = (const float*)d_in[1];
    const float* b1 = (const float*)d_in[2];
    const float* W2 = (const float*)d_in[3];
    const float* b2 = (const float*)d_in[4];
    const float* W3 = (const float*)d_in[5];
    const float* b3 = (const float*)d_in[6];
    const float* W4 = (const float*)d_in[7];
    const float* b4 = (const float*)d_in[8];
    float* out = (float*)d_out;

    k1_mlp<<<196, 128>>>(x, W1, b1, W2, b2, W3, b3, W4, b4);
    k2_reduce<<<512, 256>>>(x, out);
}

// round 7
// speedup vs baseline: 2.4683x; 1.2484x over previous
#include <cuda_runtime.h>
#include <cuda_bf16.h>
#include <cstdint>

// ---------------------------------------------------------------------------
// Device-global scratch (allocation-free)
// ---------------------------------------------------------------------------
__device__ float g_a[12544];                     // attention scalar per pixel
__device__ float g_invm[64];                     // 1 / sum_p a  per batch
__device__ __align__(16) __nv_bfloat16 gW1hi[64 * 2048];  // [chunk][k32][n64]
__device__ __align__(16) __nv_bfloat16 gW1lo[64 * 2048];

// ---------------------------------------------------------------------------
// Helpers
// ---------------------------------------------------------------------------
__device__ __forceinline__ uint32_t smem_u32(const void* p) {
    return (uint32_t)__cvta_generic_to_shared(p);
}
__device__ __forceinline__ void ldsm4(uint32_t& r0, uint32_t& r1, uint32_t& r2, uint32_t& r3, uint32_t a) {
    asm volatile("ldmatrix.sync.aligned.m8n8.x4.shared.b16 {%0,%1,%2,%3},[%4];"
                 : "=r"(r0), "=r"(r1), "=r"(r2), "=r"(r3) : "r"(a));
}
__device__ __forceinline__ void ldsm4t(uint32_t& r0, uint32_t& r1, uint32_t& r2, uint32_t& r3, uint32_t a) {
    asm volatile("ldmatrix.sync.aligned.m8n8.x4.trans.shared.b16 {%0,%1,%2,%3},[%4];"
                 : "=r"(r0), "=r"(r1), "=r"(r2), "=r"(r3) : "r"(a));
}
__device__ __forceinline__ void mma_bf16(float* c, const uint32_t* a, uint32_t b0, uint32_t b1) {
    asm volatile(
        "mma.sync.aligned.m16n8k16.row.col.f32.bf16.bf16.f32 "
        "{%0,%1,%2,%3},{%4,%5,%6,%7},{%8,%9},{%0,%1,%2,%3};"
        : "+f"(c[0]), "+f"(c[1]), "+f"(c[2]), "+f"(c[3])
        : "r"(a[0]), "r"(a[1]), "r"(a[2]), "r"(a[3]), "r"(b0), "r"(b1));
}
// pack two floats -> bf16x2 (f0 in low half), single-instruction
__device__ __forceinline__ uint32_t cvt_hi2(float f0, float f1) {
    uint32_t r;
    asm("cvt.rn.bf16x2.f32 %0, %1, %2;" : "=r"(r) : "f"(f1), "f"(f0));
    return r;
}
// residual pair: (f - float(hi)) packed as bf16x2, from the packed hi word
__device__ __forceinline__ uint32_t cvt_lo2(float f0, float f1, uint32_t hp) {
    float h0 = __uint_as_float(hp << 16);
    float h1 = __uint_as_float(hp & 0xFFFF0000u);
    return cvt_hi2(f0 - h0, f1 - h1);
}

// ---------------------------------------------------------------------------
// k0: split W1 into bf16 hi/lo, stored per K-chunk in smem staging layout
// ---------------------------------------------------------------------------
__global__ void __launch_bounds__(256) k0_convW(const float* __restrict__ W1) {
    int i = blockIdx.x * 256 + threadIdx.x;       // 131072 elems
    int k = i >> 6, n = i & 63;
    int chunk = k >> 5, kk = k & 31;
    float w = W1[i];
    __nv_bfloat16 h = __float2bfloat16_rn(w);
    int o = chunk * 2048 + kk * 64 + n;
    gW1hi[o] = h;
    gW1lo[o] = __float2bfloat16_rn(w - __bfloat162float(h));
}

// ---------------------------------------------------------------------------
// k1: tile 32 pixels x 64 outputs, K-chunk 32, 128 threads, grid 392.
// 4 warps, each m16 x n32.  Double-buffered, register-prefetched pipeline.
// ---------------------------------------------------------------------------
#define APITCH 40
#define BPITCH 72
#define AHI 0
#define ALO 2560                  // 32*40*2
#define BHI 5120
#define BLO 9728                  // + 32*72*2
#define STG 14336

__global__ void __launch_bounds__(128) k1_mlp(
    const float* __restrict__ x,
    const float* __restrict__ b1,
    const float* __restrict__ W2, const float* __restrict__ b2,
    const float* __restrict__ W3, const float* __restrict__ b3,
    const float* __restrict__ W4, const float* __restrict__ b4)
{
    __shared__ __align__(16) char sStage[2][STG];   // 28672 B
    __shared__ float sW2[64 * 16];
    __shared__ float sW3[16 * 8];
    __shared__ float sW4[8];
    __shared__ float sB1[64];

    const int tid  = threadIdx.x;
    const int lane = tid & 31;
    const int warp = tid >> 5;
    const int wm16 = (warp >> 1) * 16;          // 0 or 16
    const int wn32 = (warp & 1) * 32;           // 0 or 32
    const int m_base = blockIdx.x * 32;

    const int lkr = (lane & 7) + ((lane >> 3) & 1) * 8;   // 0..15
    const int lnc = (lane >> 4) * 8;                       // 0 or 8

    // staging coords
    const int a_row = tid >> 2;                 // 0..31
    const int a_kq  = (tid & 3) * 8;            // k offset {0,8,16,24}
    const int b_row = tid >> 2;                 // 0..31 (k within chunk)
    const int b_col = (tid & 3) * 16;           // n offset {0,16,32,48}

    for (int i = tid; i < 64 * 16; i += 128) sW2[i] = W2[i];
    if (tid < 128) sW3[tid] = W3[tid];
    if (tid < 64)  sB1[tid] = b1[tid];
    if (tid < 8)   sW4[tid] = W4[tid];

    float acc[4][4];
#pragma unroll
    for (int j = 0; j < 4; j++)
#pragma unroll
        for (int i = 0; i < 4; i++) acc[j][i] = 0.f;

    const float* aBase = x + (size_t)(m_base + a_row) * 2048 + a_kq;
    const int    bOff  = b_row * 64 + b_col;

    float4 ra[2];
    uint4  rwh[2], rwl[2];

    auto ldg_chunk = [&](int i) {
        const float4* ap = (const float4*)(aBase + (size_t)i * 32);
        ra[0] = ap[0];
        ra[1] = ap[1];
        const uint4* wh = (const uint4*)(gW1hi + i * 2048 + bOff);
        const uint4* wl = (const uint4*)(gW1lo + i * 2048 + bOff);
        rwh[0] = wh[0]; rwh[1] = wh[1];
        rwl[0] = wl[0]; rwl[1] = wl[1];
    };
    auto sts_chunk = [&](int buf) {
        char* st = sStage[buf];
        // A: 8 floats -> hi/lo bf16x2
        uint32_t h0 = cvt_hi2(ra[0].x, ra[0].y);
        uint32_t h1 = cvt_hi2(ra[0].z, ra[0].w);
        uint32_t h2 = cvt_hi2(ra[1].x, ra[1].y);
        uint32_t h3 = cvt_hi2(ra[1].z, ra[1].w);
        uint32_t l0 = cvt_lo2(ra[0].x, ra[0].y, h0);
        uint32_t l1 = cvt_lo2(ra[0].z, ra[0].w, h1);
        uint32_t l2 = cvt_lo2(ra[1].x, ra[1].y, h2);
        uint32_t l3 = cvt_lo2(ra[1].z, ra[1].w, h3);
        uint32_t aoff = (uint32_t)(a_row * APITCH + a_kq) * 2;
        *(uint4*)(st + AHI + aoff) = make_uint4(h0, h1, h2, h3);
        *(uint4*)(st + ALO + aoff) = make_uint4(l0, l1, l2, l3);
        // B: straight copies (pre-split by k0)
        uint32_t boff = (uint32_t)(b_row * BPITCH + b_col) * 2;
        *(uint4*)(st + BHI + boff)      = rwh[0];
        *(uint4*)(st + BHI + boff + 16) = rwh[1];
        *(uint4*)(st + BLO + boff)      = rwl[0];
        *(uint4*)(st + BLO + boff + 16) = rwl[1];
    };

    ldg_chunk(0);
    sts_chunk(0);
    __syncthreads();
    ldg_chunk(1);

    for (int i = 0; i < 64; i++) {
        const int cur = i & 1;
        if (i < 63) sts_chunk(cur ^ 1);
        if (i < 62) ldg_chunk(i + 2);

        const uint32_t sb = smem_u32(sStage[cur]);
#pragma unroll
        for (int kk = 0; kk < 32; kk += 16) {
            uint32_t ah[4], al[4];
            uint32_t ao = sb + AHI + (uint32_t)((wm16 + lkr) * APITCH + kk + lnc) * 2;
            ldsm4(ah[0], ah[1], ah[2], ah[3], ao);
            ldsm4(al[0], al[1], al[2], al[3], ao + (ALO - AHI));

            uint32_t bh[8], bl[8];
            uint32_t bo = sb + BHI + (uint32_t)((kk + lkr) * BPITCH + wn32 + lnc) * 2;
            ldsm4t(bh[0], bh[1], bh[2], bh[3], bo);
            ldsm4t(bh[4], bh[5], bh[6], bh[7], bo + 32);
            ldsm4t(bl[0], bl[1], bl[2], bl[3], bo + (BLO - BHI));
            ldsm4t(bl[4], bl[5], bl[6], bl[7], bo + (BLO - BHI) + 32);
#pragma unroll
            for (int j = 0; j < 4; j++) {
                float* c = acc[j];
                mma_bf16(c, ah, bh[2 * j], bh[2 * j + 1]);   // hi*hi
                mma_bf16(c, ah, bl[2 * j], bl[2 * j + 1]);   // hi*lo
                mma_bf16(c, al, bh[2 * j], bh[2 * j + 1]);   // lo*hi
            }
        }
        __syncthreads();
    }

    // epilogue: bias + relu -> sH (aliased onto stage buffers)
    float* sH = (float*)sStage[0];            // [32][65]
    {
        const int r0 = wm16 + (lane >> 2);
        const int c0 = (lane & 3) * 2;
#pragma unroll
        for (int j = 0; j < 4; j++) {
            const int n = wn32 + j * 8 + c0;
            sH[r0 * 65 + n]           = fmaxf(acc[j][0] + sB1[n],     0.f);
            sH[r0 * 65 + n + 1]       = fmaxf(acc[j][1] + sB1[n + 1], 0.f);
            sH[(r0 + 8) * 65 + n]     = fmaxf(acc[j][2] + sB1[n],     0.f);
            sH[(r0 + 8) * 65 + n + 1] = fmaxf(acc[j][3] + sB1[n + 1], 0.f);
        }
    }
    __syncthreads();

    // tail MLP: 64->16->8->1 + sigmoid, one pixel per thread
    if (tid < 32) {
        const int m = tid;
        float h2[16];
#pragma unroll
        for (int j = 0; j < 16; j++) h2[j] = b2[j];
#pragma unroll 8
        for (int n = 0; n < 64; n++) {
            float hv = sH[m * 65 + n];
#pragma unroll
            for (int j = 0; j < 16; j++) h2[j] += hv * sW2[n * 16 + j];
        }
        float h3[8];
#pragma unroll
        for (int j = 0; j < 8; j++) h3[j] = b3[j];
#pragma unroll
        for (int n = 0; n < 16; n++) {
            float hv = fmaxf(h2[n], 0.f);
#pragma unroll
            for (int j = 0; j < 8; j++) h3[j] += hv * sW3[n * 8 + j];
        }
        float z = b4[0];
#pragma unroll
        for (int n = 0; n < 8; n++) z += fmaxf(h3[n], 0.f) * sW4[n];
        g_a[m_base + m] = 1.f / (1.f + __expf(-z));
    }
}

// ---------------------------------------------------------------------------
// kz: zero out[] (float4) + compute per-batch 1/sum(a)
// ---------------------------------------------------------------------------
__global__ void __launch_bounds__(256) kz_prep(float* __restrict__ out)
{
    if (blockIdx.x < 128) {
        ((float4*)out)[blockIdx.x * 256 + threadIdx.x] = make_float4(0.f, 0.f, 0.f, 0.f);
    } else if (threadIdx.x < 64) {
        const float* a = g_a + threadIdx.x * 196;
        float s = 0.f;
#pragma unroll 14
        for (int p = 0; p < 196; p++) s += a[p];
        g_invm[threadIdx.x] = 1.f / s;
    }
}

// ---------------------------------------------------------------------------
// k2: out[b,c] += invm[b] * sum_{p in split} a_p * x[b,p,c]
// grid 1024 = 64 batches x 8 channel chunks x 2 pixel splits.
// ---------------------------------------------------------------------------
__global__ void __launch_bounds__(256) k2_reduce(
    const float* __restrict__ x, float* __restrict__ out)
{
    __shared__ float sa[98];
    __shared__ float sinv;
    const int b     = blockIdx.x >> 4;
    const int rem   = blockIdx.x & 15;
    const int chunk = rem >> 1;
    const int split = rem & 1;
    const int p0    = split * 98;

    if (threadIdx.x < 98) sa[threadIdx.x] = g_a[b * 196 + p0 + threadIdx.x];
    if (threadIdx.x == 128) sinv = g_invm[b];
    __syncthreads();

    const int ch = chunk * 256 + threadIdx.x;
    const float* xp = x + (size_t)b * 196 * 2048 + (size_t)p0 * 2048 + ch;

    float acc = 0.f;
#pragma unroll 14
    for (int p = 0; p < 98; p++) acc += sa[p] * xp[(size_t)p * 2048];

    atomicAdd(out + b * 2048 + ch, acc * sinv);
}

extern "C" void kernel_launch(void* const* d_in, const int* in_sizes, int n_in,
                              void* d_out, int out_size)
{
    const float* x  = (const float*)d_in[0];
    const float* W1 = (const float*)d_in[1];
    const float* b1 = (const float*)d_in[2];
    const float* W2 = (const float*)d_in[3];
    const float* b2 = (const float*)d_in[4];
    const float* W3 = (const float*)d_in[5];
    const float* b3 = (const float*)d_in[6];
    const float* W4 = (const float*)d_in[7];
    const float* b4 = (const float*)d_in[8];
    float* out = (float*)d_out;

    k0_convW<<<512, 256>>>(W1);
    k1_mlp<<<392, 128>>>(x, b1, W2, b2, W3, b3, W4, b4);
    kz_prep<<<129, 256>>>(out);
    k2_reduce<<<1024, 256>>>(x, out);
}

// round 8
// speedup vs baseline: 2.6044x; 1.0551x over previous
#include <cuda_runtime.h>
#include <cuda_bf16.h>
#include <cstdint>

// ---------------------------------------------------------------------------
// Device-global scratch (allocation-free)
// ---------------------------------------------------------------------------
__device__ float g_a[12544];                     // attention scalar per pixel
__device__ float g_invm[64];                     // 1 / sum_p a  per batch
__device__ float g_h1[12544 * 64];               // layer-1 pre-activation accum
__device__ __align__(16) __nv_bfloat16 gW1hi[64 * 2048];  // [chunk][k32][n64]
__device__ __align__(16) __nv_bfloat16 gW1lo[64 * 2048];

// ---------------------------------------------------------------------------
// Helpers
// ---------------------------------------------------------------------------
__device__ __forceinline__ uint32_t smem_u32(const void* p) {
    return (uint32_t)__cvta_generic_to_shared(p);
}
__device__ __forceinline__ void ldsm4(uint32_t& r0, uint32_t& r1, uint32_t& r2, uint32_t& r3, uint32_t a) {
    asm volatile("ldmatrix.sync.aligned.m8n8.x4.shared.b16 {%0,%1,%2,%3},[%4];"
                 : "=r"(r0), "=r"(r1), "=r"(r2), "=r"(r3) : "r"(a));
}
__device__ __forceinline__ void ldsm4t(uint32_t& r0, uint32_t& r1, uint32_t& r2, uint32_t& r3, uint32_t a) {
    asm volatile("ldmatrix.sync.aligned.m8n8.x4.trans.shared.b16 {%0,%1,%2,%3},[%4];"
                 : "=r"(r0), "=r"(r1), "=r"(r2), "=r"(r3) : "r"(a));
}
__device__ __forceinline__ void mma_bf16(float* c, const uint32_t* a, uint32_t b0, uint32_t b1) {
    asm volatile(
        "mma.sync.aligned.m16n8k16.row.col.f32.bf16.bf16.f32 "
        "{%0,%1,%2,%3},{%4,%5,%6,%7},{%8,%9},{%0,%1,%2,%3};"
        : "+f"(c[0]), "+f"(c[1]), "+f"(c[2]), "+f"(c[3])
        : "r"(a[0]), "r"(a[1]), "r"(a[2]), "r"(a[3]), "r"(b0), "r"(b1));
}
__device__ __forceinline__ uint32_t cvt_hi2(float f0, float f1) {
    uint32_t r;
    asm("cvt.rn.bf16x2.f32 %0, %1, %2;" : "=r"(r) : "f"(f1), "f"(f0));
    return r;
}
__device__ __forceinline__ uint32_t cvt_lo2(float f0, float f1, uint32_t hp) {
    float h0 = __uint_as_float(hp << 16);
    float h1 = __uint_as_float(hp & 0xFFFF0000u);
    return cvt_hi2(f0 - h0, f1 - h1);
}

// ---------------------------------------------------------------------------
// k0: split W1 into bf16 hi/lo in per-chunk staging layout
// ---------------------------------------------------------------------------
__global__ void __launch_bounds__(256) k0_convW(const float* __restrict__ W1) {
    int i = blockIdx.x * 256 + threadIdx.x;       // 131072 elems
    int k = i >> 6, n = i & 63;
    int chunk = k >> 5, kk = k & 31;
    float w = W1[i];
    __nv_bfloat16 h = __float2bfloat16_rn(w);
    int o = chunk * 2048 + kk * 64 + n;
    gW1hi[o] = h;
    gW1lo[o] = __float2bfloat16_rn(w - __bfloat162float(h));
}

// ---------------------------------------------------------------------------
// kzh: zero the h1 accumulator
// ---------------------------------------------------------------------------
__global__ void __launch_bounds__(256) kzh_zero() {
    ((float4*)g_h1)[blockIdx.x * 256 + threadIdx.x] = make_float4(0.f, 0.f, 0.f, 0.f);
}

// ---------------------------------------------------------------------------
// k1: split-K GEMM.  grid 784 = 392 m-tiles x 2 K-halves.
// Tile 32 pixels x 64 outputs, K-chunk 32 (32 chunks per block), 128 threads,
// 4 warps each m16 x n32.  Partial fp32 h1 accumulated via atomicAdd.
// ---------------------------------------------------------------------------
#define APITCH 40
#define BPITCH 72
#define AHI 0
#define ALO 2560                  // 32*40*2
#define BHI 5120
#define BLO 9728                  // + 32*72*2
#define STG 14336

__global__ void __launch_bounds__(128) k1_gemm(const float* __restrict__ x)
{
    __shared__ __align__(16) char sStage[2][STG];   // 28672 B

    const int tid  = threadIdx.x;
    const int lane = tid & 31;
    const int warp = tid >> 5;
    const int wm16 = (warp >> 1) * 16;          // 0 or 16
    const int wn32 = (warp & 1) * 32;           // 0 or 32
    const int m_base = (blockIdx.x >> 1) * 32;
    const int split  = blockIdx.x & 1;          // K half

    const int lkr = (lane & 7) + ((lane >> 3) & 1) * 8;   // 0..15
    const int lnc = (lane >> 4) * 8;                       // 0 or 8

    const int a_row = tid >> 2;                 // 0..31
    const int a_kq  = (tid & 3) * 8;            // k offset {0,8,16,24}
    const int b_row = tid >> 2;                 // 0..31
    const int b_col = (tid & 3) * 16;           // n offset {0,16,32,48}

    float acc[4][4];
#pragma unroll
    for (int j = 0; j < 4; j++)
#pragma unroll
        for (int i = 0; i < 4; i++) acc[j][i] = 0.f;

    const float* aBase = x + (size_t)(m_base + a_row) * 2048 + split * 1024 + a_kq;
    const __nv_bfloat16* whBase = gW1hi + (split * 32) * 2048 + b_row * 64 + b_col;
    const __nv_bfloat16* wlBase = gW1lo + (split * 32) * 2048 + b_row * 64 + b_col;

    float4 ra[2];
    uint4  rwh[2], rwl[2];

    auto ldg_chunk = [&](int i) {
        const float4* ap = (const float4*)(aBase + (size_t)i * 32);
        ra[0] = ap[0];
        ra[1] = ap[1];
        const uint4* wh = (const uint4*)(whBase + i * 2048);
        const uint4* wl = (const uint4*)(wlBase + i * 2048);
        rwh[0] = wh[0]; rwh[1] = wh[1];
        rwl[0] = wl[0]; rwl[1] = wl[1];
    };
    auto sts_chunk = [&](int buf) {
        char* st = sStage[buf];
        uint32_t h0 = cvt_hi2(ra[0].x, ra[0].y);
        uint32_t h1 = cvt_hi2(ra[0].z, ra[0].w);
        uint32_t h2 = cvt_hi2(ra[1].x, ra[1].y);
        uint32_t h3 = cvt_hi2(ra[1].z, ra[1].w);
        uint32_t l0 = cvt_lo2(ra[0].x, ra[0].y, h0);
        uint32_t l1 = cvt_lo2(ra[0].z, ra[0].w, h1);
        uint32_t l2 = cvt_lo2(ra[1].x, ra[1].y, h2);
        uint32_t l3 = cvt_lo2(ra[1].z, ra[1].w, h3);
        uint32_t aoff = (uint32_t)(a_row * APITCH + a_kq) * 2;
        *(uint4*)(st + AHI + aoff) = make_uint4(h0, h1, h2, h3);
        *(uint4*)(st + ALO + aoff) = make_uint4(l0, l1, l2, l3);
        uint32_t boff = (uint32_t)(b_row * BPITCH + b_col) * 2;
        *(uint4*)(st + BHI + boff)      = rwh[0];
        *(uint4*)(st + BHI + boff + 16) = rwh[1];
        *(uint4*)(st + BLO + boff)      = rwl[0];
        *(uint4*)(st + BLO + boff + 16) = rwl[1];
    };

    ldg_chunk(0);
    sts_chunk(0);
    __syncthreads();
    ldg_chunk(1);

    for (int i = 0; i < 32; i++) {
        const int cur = i & 1;
        if (i < 31) sts_chunk(cur ^ 1);
        if (i < 30) ldg_chunk(i + 2);

        const uint32_t sb = smem_u32(sStage[cur]);
#pragma unroll
        for (int kk = 0; kk < 32; kk += 16) {
            uint32_t ah[4], al[4];
            uint32_t ao = sb + AHI + (uint32_t)((wm16 + lkr) * APITCH + kk + lnc) * 2;
            ldsm4(ah[0], ah[1], ah[2], ah[3], ao);
            ldsm4(al[0], al[1], al[2], al[3], ao + (ALO - AHI));

            uint32_t bh[8], bl[8];
            uint32_t bo = sb + BHI + (uint32_t)((kk + lkr) * BPITCH + wn32 + lnc) * 2;
            ldsm4t(bh[0], bh[1], bh[2], bh[3], bo);
            ldsm4t(bh[4], bh[5], bh[6], bh[7], bo + 32);
            ldsm4t(bl[0], bl[1], bl[2], bl[3], bo + (BLO - BHI));
            ldsm4t(bl[4], bl[5], bl[6], bl[7], bo + (BLO - BHI) + 32);
#pragma unroll
            for (int j = 0; j < 4; j++) {
                float* c = acc[j];
                mma_bf16(c, ah, bh[2 * j], bh[2 * j + 1]);   // hi*hi
                mma_bf16(c, ah, bl[2 * j], bl[2 * j + 1]);   // hi*lo
                mma_bf16(c, al, bh[2 * j], bh[2 * j + 1]);   // lo*hi
            }
        }
        __syncthreads();
    }

    // epilogue: accumulate partial h1 (fp32, 2 commutative adds per element)
    {
        const int r0 = m_base + wm16 + (lane >> 2);
        const int c0 = (lane & 3) * 2;
#pragma unroll
        for (int j = 0; j < 4; j++) {
            const int n = wn32 + j * 8 + c0;
            atomicAdd(&g_h1[r0 * 64 + n],           acc[j][0]);
            atomicAdd(&g_h1[r0 * 64 + n + 1],       acc[j][1]);
            atomicAdd(&g_h1[(r0 + 8) * 64 + n],     acc[j][2]);
            atomicAdd(&g_h1[(r0 + 8) * 64 + n + 1], acc[j][3]);
        }
    }
}

// ---------------------------------------------------------------------------
// k1b: per-batch tail.  grid 64, 224 threads.  bias+relu+MLP+sigmoid per
// pixel, write g_a, reduce 1/sum(a) -> g_invm, zero out[b] slice.
// ---------------------------------------------------------------------------
__global__ void __launch_bounds__(224) k1b_tail(
    const float* __restrict__ b1,
    const float* __restrict__ W2, const float* __restrict__ b2,
    const float* __restrict__ W3, const float* __restrict__ b3,
    const float* __restrict__ W4, const float* __restrict__ b4,
    float* __restrict__ out)
{
    __shared__ float sW2[64 * 16];
    __shared__ float sW3[16 * 8];
    __shared__ float sW4[8];
    __shared__ float sB1[64];
    __shared__ float swsum[7];

    const int b = blockIdx.x;
    const int t = threadIdx.x;

    for (int i = t; i < 64 * 16; i += 224) sW2[i] = W2[i];
    if (t < 128) sW3[t] = W3[t];
    if (t < 64)  sB1[t] = b1[t];
    if (t < 8)   sW4[t] = W4[t];
    for (int i = t; i < 2048; i += 224) out[b * 2048 + i] = 0.f;
    __syncthreads();

    float a = 0.f;
    if (t < 196) {
        const int pixel = b * 196 + t;
        const float4* hp = (const float4*)(g_h1 + (size_t)pixel * 64);
        float h2[16];
#pragma unroll
        for (int j = 0; j < 16; j++) h2[j] = b2[j];
#pragma unroll
        for (int q = 0; q < 16; q++) {
            float4 v = hp[q];
            float hv0 = fmaxf(v.x + sB1[q * 4 + 0], 0.f);
            float hv1 = fmaxf(v.y + sB1[q * 4 + 1], 0.f);
            float hv2 = fmaxf(v.z + sB1[q * 4 + 2], 0.f);
            float hv3 = fmaxf(v.w + sB1[q * 4 + 3], 0.f);
#pragma unroll
            for (int j = 0; j < 16; j++) {
                h2[j] += hv0 * sW2[(q * 4 + 0) * 16 + j];
                h2[j] += hv1 * sW2[(q * 4 + 1) * 16 + j];
                h2[j] += hv2 * sW2[(q * 4 + 2) * 16 + j];
                h2[j] += hv3 * sW2[(q * 4 + 3) * 16 + j];
            }
        }
        float h3[8];
#pragma unroll
        for (int j = 0; j < 8; j++) h3[j] = b3[j];
#pragma unroll
        for (int n = 0; n < 16; n++) {
            float hv = fmaxf(h2[n], 0.f);
#pragma unroll
            for (int j = 0; j < 8; j++) h3[j] += hv * sW3[n * 8 + j];
        }
        float z = b4[0];
#pragma unroll
        for (int n = 0; n < 8; n++) z += fmaxf(h3[n], 0.f) * sW4[n];
        a = 1.f / (1.f + __expf(-z));
        g_a[pixel] = a;
    }

    // block reduction of sum(a)
    float s = a;
#pragma unroll
    for (int o = 16; o; o >>= 1) s += __shfl_down_sync(0xFFFFFFFFu, s, o);
    if ((t & 31) == 0) swsum[t >> 5] = s;
    __syncthreads();
    if (t == 0) {
        float tot = 0.f;
#pragma unroll
        for (int w = 0; w < 7; w++) tot += swsum[w];
        g_invm[b] = 1.f / tot;
    }
}

// ---------------------------------------------------------------------------
// k2: out[b,c] += invm[b] * sum_{p in split} a_p * x[b,p,c]
// grid 1024 = 64 batches x 8 channel chunks x 2 pixel splits.
// ---------------------------------------------------------------------------
__global__ void __launch_bounds__(256) k2_reduce(
    const float* __restrict__ x, float* __restrict__ out)
{
    __shared__ float sa[98];
    __shared__ float sinv;
    const int b     = blockIdx.x >> 4;
    const int rem   = blockIdx.x & 15;
    const int chunk = rem >> 1;
    const int split = rem & 1;
    const int p0    = split * 98;

    if (threadIdx.x < 98) sa[threadIdx.x] = g_a[b * 196 + p0 + threadIdx.x];
    if (threadIdx.x == 128) sinv = g_invm[b];
    __syncthreads();

    const int ch = chunk * 256 + threadIdx.x;
    const float* xp = x + (size_t)b * 196 * 2048 + (size_t)p0 * 2048 + ch;

    float acc0 = 0.f, acc1 = 0.f;
#pragma unroll 7
    for (int p = 0; p < 98; p += 2) {
        acc0 += sa[p]     * xp[(size_t)p * 2048];
        acc1 += sa[p + 1] * xp[(size_t)(p + 1) * 2048];
    }
    atomicAdd(out + b * 2048 + ch, (acc0 + acc1) * sinv);
}

extern "C" void kernel_launch(void* const* d_in, const int* in_sizes, int n_in,
                              void* d_out, int out_size)
{
    const float* x  = (const float*)d_in[0];
    const float* W1 = (const float*)d_in[1];
    const float* b1 = (const float*)d_in[2];
    const float* W2 = (const float*)d_in[3];
    const float* b2 = (const float*)d_in[4];
    const float* W3 = (const float*)d_in[5];
    const float* b3 = (const float*)d_in[6];
    const float* W4 = (const float*)d_in[7];
    const float* b4 = (const float*)d_in[8];
    float* out = (float*)d_out;

    k0_convW<<<512, 256>>>(W1);
    kzh_zero<<<784, 256>>>();
    k1_gemm<<<784, 128>>>(x);
    k1b_tail<<<64, 224>>>(b1, W2, b2, W3, b3, W4, b4, out);
    k2_reduce<<<1024, 256>>>(x, out);
}